// round 8
// baseline (speedup 1.0000x reference)
#include <cuda_runtime.h>
#include <cstdint>

#define DIMC 384
#define G    48                  // channels per CTA (8-CTA cluster covers 384)
#define NP   49
#define HW   112
#define CH_STRIDE (112 * 112)
#define NT   1024
#define CHUNK 12                 // channels per pipeline chunk
#define NCHUNK 4
#define CHUNK_F4 (CHUNK * 196)   // 2352 float4 per chunk (784 floats/channel)

__global__ void __launch_bounds__(NT, 1) __cluster_dims__(8, 1, 1)
attn_ds_kernel(
    const float* __restrict__ hr,   // (8, 384, 112, 112)
    const float* __restrict__ du,   // (8, 16, 16, 1)
    const float* __restrict__ aw,   // (384,)
    const float* __restrict__ ab,   // (1,)
    const float* __restrict__ wt,   // (7,7) -> 49
    const float* __restrict__ bt,   // (7,7) -> 49
    float* __restrict__ out)        // (8, 384, 16, 16)
{
    extern __shared__ float s_strip[];        // [48][784] = 150528 B
    __shared__ float s_red[8][784];           // partial logits from all 8 ranks
    __shared__ float s_logits[784];           // [w][p] pixel-major
    __shared__ float s_attn[784];             // [w][p]
    __shared__ float s_aw[G];

    const int tid  = threadIdx.x;
    const int lane = tid & 31;
    const int wid  = tid >> 5;
    const int rank  = blockIdx.x & 7;         // channel group
    const int strip = blockIdx.x >> 3;        // b*16 + h
    const int b = strip >> 4;
    const int h = strip & 15;
    const int c0 = rank * G;

    if (tid < G) s_aw[tid] = aw[c0 + tid];

    // phase-2 thread mapping: tid = p*16 + w (tid < 784)
    const int w_ = tid & 15;
    const int p_ = tid >> 4;
    const int pos = (p_ / 7) * HW + (p_ % 7) + 7 * w_;   // (y,x) in strip

    // Channel c's strip (rows 7h..7h+6) is ONE contiguous 784-float block.
    const float4* gsrc = (const float4*)hr
        + ((size_t)b * DIMC + c0) * (CH_STRIDE / 4) + (size_t)h * 196;

    // ---- Pipelined load (float4, fully coalesced) + partial-logit compute ----
    //   idx/196 via magic: c = (idx*85599)>>24  (exact for idx < 3000)
    float4 va[3], vb[3];
    #pragma unroll
    for (int i = 0; i < 3; ++i) {
        unsigned idx = (unsigned)tid + i * NT;
        if (idx < CHUNK_F4) {
            unsigned c = (idx * 85599u) >> 24;
            unsigned r = idx - c * 196u;
            va[i] = gsrc[(size_t)c * 3136 + r];
        }
    }
    float acc = 0.0f;
    #pragma unroll
    for (int k = 0; k < NCHUNK; ++k) {
        if (k + 1 < NCHUNK) {                 // prefetch next chunk into regs
            #pragma unroll
            for (int i = 0; i < 3; ++i) {
                unsigned idx = (unsigned)tid + i * NT;
                if (idx < CHUNK_F4) {
                    unsigned c = (idx * 85599u) >> 24;
                    unsigned r = idx - c * 196u;
                    vb[i] = gsrc[(size_t)((k + 1) * CHUNK + c) * 3136 + r];
                }
            }
        }
        #pragma unroll
        for (int i = 0; i < 3; ++i) {         // drain current chunk to SMEM
            unsigned idx = (unsigned)tid + i * NT;
            if (idx < CHUNK_F4) {
                unsigned c = (idx * 85599u) >> 24;
                unsigned r = idx - c * 196u;
                ((float4*)s_strip)[(k * CHUNK + c) * 196 + r] = va[i];
            }
        }
        __syncthreads();
        if (tid < 784) {                      // partial logits for this chunk
            #pragma unroll
            for (int c = 0; c < CHUNK; ++c) {
                int cc = k * CHUNK + c;
                acc = fmaf(s_strip[cc * 784 + pos], s_aw[cc], acc);
            }
        }
        #pragma unroll
        for (int i = 0; i < 3; ++i) va[i] = vb[i];
    }

    // ---- All-to-all: push own 784 partials into every peer's s_red[rank] ----
    if (tid < 784) {
        s_red[rank][tid] = acc;               // own slot locally
        uint32_t loc = (uint32_t)__cvta_generic_to_shared(&s_red[rank][tid]);
        #pragma unroll
        for (int pr = 0; pr < 8; ++pr) {
            if (pr == rank) continue;
            uint32_t rem;
            asm ("mapa.shared::cluster.u32 %0, %1, %2;" : "=r"(rem) : "r"(loc), "r"(pr));
            asm volatile("st.shared::cluster.f32 [%0], %1;" :: "r"(rem), "f"(acc) : "memory");
        }
    }
    asm volatile("barrier.cluster.arrive.aligned;" ::: "memory");
    asm volatile("barrier.cluster.wait.aligned;"   ::: "memory");

    // ---- Combine 8 partials, scatter to pixel-major layout ----
    if (tid < 784) {
        float tot = 0.0f;
        #pragma unroll
        for (int r = 0; r < 8; ++r) tot += s_red[r][tid];
        s_logits[w_ * 49 + p_] = tot;         // banks 17*l bijective: conflict-free
    }
    __syncthreads();

    // ---- Softmax per pixel: warp wid handles pixel w = wid ----
    if (wid < 16) {
        const float m   = (du[(b * 16 + h) * 16 + wid] > 0.2f) ? 1.0f : 0.0f;
        const float a0c = ab[0];
        const int p1 = lane + 32;
        float l0 = (s_logits[wid * 49 + lane] + a0c) * m * wt[lane] + bt[lane];
        float l1 = (p1 < NP)
                 ? (s_logits[wid * 49 + p1] + a0c) * m * wt[p1] + bt[p1]
                 : -1e30f;
        float mx = fmaxf(l0, l1);
        #pragma unroll
        for (int o = 16; o > 0; o >>= 1)
            mx = fmaxf(mx, __shfl_xor_sync(0xffffffffu, mx, o));
        float e0 = __expf(l0 - mx);
        float e1 = (p1 < NP) ? __expf(l1 - mx) : 0.0f;
        float s = e0 + e1;
        #pragma unroll
        for (int o = 16; o > 0; o >>= 1)
            s += __shfl_xor_sync(0xffffffffu, s, o);
        const float inv = 1.0f / s;
        s_attn[wid * 49 + lane] = e0 * inv;
        if (p1 < NP) s_attn[wid * 49 + p1] = e1 * inv;
    }
    __syncthreads();

    // ---- Phase 4: out[c][w] = sum_p strip[c][pos(w,p)] * attn[w][p] ----
    // thread = (c, w); banks 7w (7 coprime 32) + c*784 (=16 mod 32): bijective.
    if (tid < 768) {
        const int c = tid >> 4;               // 0..47
        const int w = tid & 15;
        const float* sp = s_strip + c * 784 + 7 * w;
        const float* at = s_attn + w * 49;
        float a0 = 0.0f, a1 = 0.0f;
        #pragma unroll
        for (int p = 0; p < NP; ++p) {
            const int off = (p / 7) * HW + (p % 7);   // compile-time constant
            if (p & 1) a1 = fmaf(sp[off], at[p], a1);
            else       a0 = fmaf(sp[off], at[p], a0);
        }
        __stcg(&out[(((size_t)b * DIMC + c0 + c) * 16 + h) * 16 + w], a0 + a1);
    }
}

extern "C" void kernel_launch(void* const* d_in, const int* in_sizes, int n_in,
                              void* d_out, int out_size)
{
    const float* hr = (const float*)d_in[0];  // hr_feats
    // d_in[1] = guidance (unused, zeros)
    const float* du = (const float*)d_in[2];  // dropout_u
    const float* aw = (const float*)d_in[3];
    const float* ab = (const float*)d_in[4];
    const float* wt = (const float*)d_in[5];
    const float* bt = (const float*)d_in[6];
    float* out = (float*)d_out;

    const size_t smem = (size_t)G * 784 * sizeof(float);   // 150528 B dynamic
    cudaFuncSetAttribute(attn_ds_kernel,
                         cudaFuncAttributeMaxDynamicSharedMemorySize, (int)smem);
    // 128 strips (b,h) x 8-CTA clusters = 1024 CTAs, 1024 threads each.
    attn_ds_kernel<<<1024, NT, smem>>>(hr, du, aw, ab, wt, bt, out);
}

// round 9
// speedup vs baseline: 1.3240x; 1.3240x over previous
#include <cuda_runtime.h>
#include <cstdint>

#define DIMC 384
#define G     192        // channels per CTA (cluster of 2 covers 384)
#define NP    49
#define PITCH 196        // floats per channel in s_raw: 4 pixels x 49
#define NT    1024
#define HALF_F4 4704     // 96 channels x 49 float4

__global__ void __launch_bounds__(NT, 1) __cluster_dims__(2, 1, 1)
attn_ds_kernel(
    const float* __restrict__ hr,   // (8, 384, 112, 112)
    const float* __restrict__ du,   // (8, 16, 16, 1)
    const float* __restrict__ aw,   // (384,)
    const float* __restrict__ ab,   // (1,)
    const float* __restrict__ wt,   // (7,7) -> 49
    const float* __restrict__ bt,   // (7,7) -> 49
    float* __restrict__ out)        // (8, 384, 16, 16)
{
    extern __shared__ float s_raw[];          // [192][196] = 150528 B
    __shared__ float s_pl[8][196];            // phase-2 sub-partials
    __shared__ float s_part[196];             // own partial logits [p*4+w]
    __shared__ float s_peer[196];             // peer partials (remote-written)
    __shared__ float s_attn[196];             // attn weights [p*4+w]
    __shared__ float s_aw[G];

    const int tid  = threadIdx.x;
    const int lane = tid & 31;
    const int wid  = tid >> 5;
    const int rank = blockIdx.x & 1;          // channel half
    const int grp  = blockIdx.x >> 1;         // (b*16+h)*4 + q
    const int q    = grp & 3;                 // pixel-quad: pixels 4q..4q+3
    const int strip= grp >> 2;                // b*16 + h
    const int b = strip >> 4, h = strip & 15;
    const int c0 = rank * G;

    if (tid < G) s_aw[tid] = aw[c0 + tid];

    // Channel c's 4-pixel patch row = 28 contiguous floats = 7 aligned float4.
    // f4 addr = (b*384+c0+c)*3136 + (7h+row)*28 + 7q + f4c
    const float4* gsrc = (const float4*)hr
        + ((size_t)(b * DIMC + c0)) * 3136 + (size_t)h * 196 + q * 7;
    float4* s4 = (float4*)s_raw;

    // ---- Load chunk A (c in [0,96)): fully coalesced LDG.128 ----
    //   c = idx/49 via (idx*42800)>>21 (exact idx<43690); row = rem/7 via
    //   (rem*9363)>>16; 4704 = 4*1024 + 608.
    float4 v[5];
    #pragma unroll
    for (int i = 0; i < 5; ++i) {
        unsigned idx = (unsigned)tid + i * NT;
        if (i < 4 || tid < 608) {
            unsigned c  = (idx * 42800u) >> 21;
            unsigned rm = idx - c * 49u;
            unsigned rw = (rm * 9363u) >> 16;
            unsigned fc = rm - rw * 7u;
            v[i] = gsrc[(size_t)c * 3136 + rw * 28 + fc];
        }
    }
    #pragma unroll
    for (int i = 0; i < 5; ++i)
        if (i < 4 || tid < 608) s4[tid + i * NT] = v[i];   // contiguous STS.128

    // ---- Issue chunk B loads (c in [96,192)) before computing on A ----
    float4 v2[5];
    #pragma unroll
    for (int i = 0; i < 5; ++i) {
        unsigned idx = HALF_F4 + (unsigned)tid + i * NT;
        if (i < 4 || tid < 608) {
            unsigned c  = (idx * 42800u) >> 21;
            unsigned rm = idx - c * 49u;
            unsigned rw = (rm * 9363u) >> 16;
            unsigned fc = rm - rw * 7u;
            v2[i] = gsrc[(size_t)c * 3136 + rw * 28 + fc];
        }
    }
    __syncthreads();                          // chunk A visible to all

    // ---- Phase 2A: partial logits over c in [0,96) (hides chunk-B DRAM) ----
    // Warp (g = wid%7, cc = wid/7); lane<28 -> slot (p = 7g + lane/4, w = lane%3..)
    // banks: (lane>>2) + 7*(lane&3) distinct on 0..27 -> conflict-free.
    if (wid < 28 && lane < 28) {
        const int g   = wid % 7;
        const int cc  = wid / 7;              // 0..3 -> 24-channel chunk
        const int off = 28 * g + (lane >> 2) + 7 * (lane & 3);
        const int cb  = cc * 24;
        float acc = 0.0f;
        #pragma unroll
        for (int i = 0; i < 24; ++i)
            acc = fmaf(s_raw[(cb + i) * PITCH + off], s_aw[cb + i], acc);
        s_pl[cc][g * 28 + lane] = acc;
    }

    // ---- Drain chunk B to SMEM ----
    #pragma unroll
    for (int i = 0; i < 5; ++i)
        if (i < 4 || tid < 608) s4[HALF_F4 + tid + i * NT] = v2[i];
    __syncthreads();

    // ---- Phase 2B: partial logits over c in [96,192) ----
    if (wid < 28 && lane < 28) {
        const int g   = wid % 7;
        const int cc  = wid / 7;
        const int off = 28 * g + (lane >> 2) + 7 * (lane & 3);
        const int cb  = 96 + cc * 24;
        float acc = 0.0f;
        #pragma unroll
        for (int i = 0; i < 24; ++i)
            acc = fmaf(s_raw[(cb + i) * PITCH + off], s_aw[cb + i], acc);
        s_pl[4 + cc][g * 28 + lane] = acc;
    }
    __syncthreads();

    // ---- Combine 8 sub-partials; push to peer CTA (other 192 channels) ----
    if (tid < 196) {
        float t = 0.0f;
        #pragma unroll
        for (int r = 0; r < 8; ++r) t += s_pl[r][tid];
        s_part[tid] = t;
        uint32_t loc = (uint32_t)__cvta_generic_to_shared(&s_peer[tid]);
        uint32_t rem;
        asm ("mapa.shared::cluster.u32 %0, %1, %2;" : "=r"(rem) : "r"(loc), "r"(rank ^ 1));
        asm volatile("st.shared::cluster.f32 [%0], %1;" :: "r"(rem), "f"(t) : "memory");
    }
    asm volatile("barrier.cluster.arrive.aligned;" ::: "memory");
    asm volatile("barrier.cluster.wait.aligned;"   ::: "memory");

    // ---- Softmax: warp wid handles pixel w = wid (4 pixels) ----
    if (wid < 4) {
        const int w = wid;
        const float m   = (du[(strip << 4) + (q << 2) + w] > 0.2f) ? 1.0f : 0.0f;
        const float a0c = ab[0];
        const int p1 = lane + 32;
        float l0 = (s_part[4 * lane + w] + s_peer[4 * lane + w] + a0c)
                   * m * wt[lane] + bt[lane];
        float l1 = (p1 < NP)
                 ? (s_part[4 * p1 + w] + s_peer[4 * p1 + w] + a0c)
                   * m * wt[p1] + bt[p1]
                 : -1e30f;
        float mx = fmaxf(l0, l1);
        #pragma unroll
        for (int o = 16; o > 0; o >>= 1)
            mx = fmaxf(mx, __shfl_xor_sync(0xffffffffu, mx, o));
        float e0 = __expf(l0 - mx);
        float e1 = (p1 < NP) ? __expf(l1 - mx) : 0.0f;
        float s = e0 + e1;
        #pragma unroll
        for (int o = 16; o > 0; o >>= 1)
            s += __shfl_xor_sync(0xffffffffu, s, o);
        const float inv = 1.0f / s;
        s_attn[4 * lane + w] = e0 * inv;
        if (p1 < NP) s_attn[4 * p1 + w] = e1 * inv;
    }
    __syncthreads();

    // ---- Phase 4: out[c][w] = sum_p patch * attn; thread = (c, w) ----
    // banks: 4*(lane>>2) + 7*(lane&3) distinct over all 32 lanes -> conflict-free.
    if (tid < 768) {
        const int c = tid >> 2;
        const int w = tid & 3;
        const float* sp = s_raw + c * PITCH + 7 * w;
        float a0 = 0.0f, a1 = 0.0f;
        #pragma unroll
        for (int p = 0; p < NP; ++p) {
            const int off = (p / 7) * 28 + (p % 7);   // compile-time
            if (p & 1) a1 = fmaf(sp[off], s_attn[4 * p + w], a1);
            else       a0 = fmaf(sp[off], s_attn[4 * p + w], a0);
        }
        __stcg(&out[(((size_t)(b * DIMC + c0 + c)) << 8) + (h << 4) + (q << 2) + w],
               a0 + a1);
    }
}

extern "C" void kernel_launch(void* const* d_in, const int* in_sizes, int n_in,
                              void* d_out, int out_size)
{
    const float* hr = (const float*)d_in[0];  // hr_feats
    // d_in[1] = guidance (unused, zeros)
    const float* du = (const float*)d_in[2];  // dropout_u
    const float* aw = (const float*)d_in[3];
    const float* ab = (const float*)d_in[4];
    const float* wt = (const float*)d_in[5];
    const float* bt = (const float*)d_in[6];
    float* out = (float*)d_out;

    const size_t smem = (size_t)G * PITCH * sizeof(float);  // 150528 B
    cudaFuncSetAttribute(attn_ds_kernel,
                         cudaFuncAttributeMaxDynamicSharedMemorySize, (int)smem);
    // 128 strips x 4 pixel-quads x 2-CTA clusters = 1024 CTAs, 1024 threads.
    attn_ds_kernel<<<1024, NT, smem>>>(hr, du, aw, ab, wt, bt, out);
}

// round 10
// speedup vs baseline: 1.5458x; 1.1675x over previous
#include <cuda_runtime.h>
#include <cstdint>

#define DIMC 384
#define G     96         // channels per CTA (cluster of 4 covers 384)
#define NP    49
#define PITCH 196        // floats per channel: 4 pixels x 49
#define NT    672        // 21 warps; 96*49 = 4704 f4 = exactly 7 per thread

__global__ void __launch_bounds__(NT, 2) __cluster_dims__(4, 1, 1)
attn_ds_kernel(
    const float* __restrict__ hr,   // (8, 384, 112, 112)
    const float* __restrict__ du,   // (8, 16, 16, 1)
    const float* __restrict__ aw,   // (384,)
    const float* __restrict__ ab,   // (1,)
    const float* __restrict__ wt,   // (7,7) -> 49
    const float* __restrict__ bt,   // (7,7) -> 49
    float* __restrict__ out)        // (8, 384, 16, 16)
{
    extern __shared__ float s_raw[];          // [96][196] = 75264 B
    __shared__ float s_pl[3][196];            // phase-2 sub-partials (3 warp-groups)
    __shared__ float s_red[4][196];           // partials from all 4 ranks
    __shared__ float s_attn[196];             // attn weights [p*4+w]
    __shared__ float s_aw[G];

    const int tid  = threadIdx.x;
    const int lane = tid & 31;
    const int wid  = tid >> 5;
    const int rank = blockIdx.x & 3;          // channel quarter
    const int grp  = blockIdx.x >> 2;         // (b*16+h)*4 + q
    const int q    = grp & 3;                 // pixel-quad: pixels 4q..4q+3
    const int strip= grp >> 2;                // b*16 + h
    const int b = strip >> 4, h = strip & 15;
    const int c0 = rank * G;

    if (tid < G) s_aw[tid] = aw[c0 + tid];

    // Channel c's 4-pixel patch row = 28 contiguous floats = 7 aligned float4.
    const float4* gsrc = (const float4*)hr
        + ((size_t)(b * DIMC + c0)) * 3136 + (size_t)h * 196 + q * 7;
    float4* s4 = (float4*)s_raw;

    // ---- Load: 4704 f4, exactly 7 per thread, fully coalesced LDG.128 ----
    //   c = idx/49 via (idx*42800)>>21 (exact idx<43690); rw = rm/7 via
    //   (rm*9363)>>16. SMEM float layout per channel: rw*28 + col (natural).
    float4 v[7];
    #pragma unroll
    for (int i = 0; i < 7; ++i) {
        unsigned idx = (unsigned)tid + i * NT;
        unsigned c  = (idx * 42800u) >> 21;
        unsigned rm = idx - c * 49u;
        unsigned rw = (rm * 9363u) >> 16;
        unsigned fc = rm - rw * 7u;
        v[i] = gsrc[(size_t)c * 3136 + rw * 28 + fc];
    }
    #pragma unroll
    for (int i = 0; i < 7; ++i)
        s4[tid + i * NT] = v[i];              // contiguous STS.128
    __syncthreads();

    // ---- Phase 2: partial logits over this CTA's 96 channels ----
    // 21 warps: g = wid%7 (p-row), cc = wid/7 (32-channel group); lane<28 ->
    // (pp = lane>>2, w = lane&3), off = 28g + pp + 7w.
    // Banks pp + 7w distinct over 28 lanes -> conflict-free.
    if (lane < 28) {
        const int g   = wid % 7;
        const int cc  = wid / 7;              // 0..2
        const int off = 28 * g + (lane >> 2) + 7 * (lane & 3);
        const int cb  = cc * 32;
        float a0 = 0.0f, a1 = 0.0f;
        #pragma unroll
        for (int i = 0; i < 32; i += 2) {
            a0 = fmaf(s_raw[(cb + i)     * PITCH + off], s_aw[cb + i],     a0);
            a1 = fmaf(s_raw[(cb + i + 1) * PITCH + off], s_aw[cb + i + 1], a1);
        }
        s_pl[cc][g * 28 + lane] = a0 + a1;    // index == 4p + w
    }
    __syncthreads();

    // ---- Combine 3 sub-partials; push to 3 peer CTAs ----
    if (tid < 196) {
        float t = s_pl[0][tid] + s_pl[1][tid] + s_pl[2][tid];
        s_red[rank][tid] = t;                 // own slot locally
        uint32_t loc = (uint32_t)__cvta_generic_to_shared(&s_red[rank][tid]);
        #pragma unroll
        for (int pr = 0; pr < 4; ++pr) {
            if (pr == rank) continue;
            uint32_t rem;
            asm ("mapa.shared::cluster.u32 %0, %1, %2;" : "=r"(rem) : "r"(loc), "r"(pr));
            asm volatile("st.shared::cluster.f32 [%0], %1;" :: "r"(rem), "f"(t) : "memory");
        }
    }
    // Cluster barrier: releases our remote stores, acquires peers' stores.
    asm volatile("barrier.cluster.arrive.aligned;" ::: "memory");
    asm volatile("barrier.cluster.wait.aligned;"   ::: "memory");

    // ---- Softmax: warp wid handles pixel w = wid (4 pixels) ----
    if (wid < 4) {
        const int w = wid;
        const float m   = (du[(strip << 4) + (q << 2) + w] > 0.2f) ? 1.0f : 0.0f;
        const float a0c = ab[0];
        const int p1 = lane + 32;
        float l0 = (s_red[0][4 * lane + w] + s_red[1][4 * lane + w]
                  + s_red[2][4 * lane + w] + s_red[3][4 * lane + w] + a0c)
                   * m * wt[lane] + bt[lane];
        float l1 = (p1 < NP)
                 ? (s_red[0][4 * p1 + w] + s_red[1][4 * p1 + w]
                  + s_red[2][4 * p1 + w] + s_red[3][4 * p1 + w] + a0c)
                   * m * wt[p1] + bt[p1]
                 : -1e30f;
        float mx = fmaxf(l0, l1);
        #pragma unroll
        for (int o = 16; o > 0; o >>= 1)
            mx = fmaxf(mx, __shfl_xor_sync(0xffffffffu, mx, o));
        float e0 = __expf(l0 - mx);
        float e1 = (p1 < NP) ? __expf(l1 - mx) : 0.0f;
        float s = e0 + e1;
        #pragma unroll
        for (int o = 16; o > 0; o >>= 1)
            s += __shfl_xor_sync(0xffffffffu, s, o);
        const float inv = 1.0f / s;
        s_attn[4 * lane + w] = e0 * inv;
        if (p1 < NP) s_attn[4 * p1 + w] = e1 * inv;
    }
    __syncthreads();

    // ---- Phase 4: out[c][w] = sum_p patch * attn; thread = (c, w) ----
    // Banks 4*(lane>>2) + 7*(lane&3) distinct over 32 lanes -> conflict-free.
    if (tid < 384) {
        const int c = tid >> 2;               // 0..95
        const int w = tid & 3;
        const float* sp = s_raw + c * PITCH + 7 * w;
        float a0 = 0.0f, a1 = 0.0f;
        #pragma unroll
        for (int p = 0; p < NP; ++p) {
            const int off = (p / 7) * 28 + (p % 7);   // compile-time
            if (p & 1) a1 = fmaf(sp[off], s_attn[4 * p + w], a1);
            else       a0 = fmaf(sp[off], s_attn[4 * p + w], a0);
        }
        __stcg(&out[(((size_t)(b * DIMC + c0 + c)) << 8) + (h << 4) + (q << 2) + w],
               a0 + a1);
    }
}

extern "C" void kernel_launch(void* const* d_in, const int* in_sizes, int n_in,
                              void* d_out, int out_size)
{
    const float* hr = (const float*)d_in[0];  // hr_feats
    // d_in[1] = guidance (unused, zeros)
    const float* du = (const float*)d_in[2];  // dropout_u
    const float* aw = (const float*)d_in[3];
    const float* ab = (const float*)d_in[4];
    const float* wt = (const float*)d_in[5];
    const float* bt = (const float*)d_in[6];
    float* out = (float*)d_out;

    const size_t smem = (size_t)G * PITCH * sizeof(float);  // 75264 B
    cudaFuncSetAttribute(attn_ds_kernel,
                         cudaFuncAttributeMaxDynamicSharedMemorySize, (int)smem);
    // 128 strips x 4 quads x 4-CTA clusters = 2048 CTAs; 2 CTAs/SM for
    // cross-CTA load/compute overlap (R9's missing ingredient).
    attn_ds_kernel<<<2048, NT, smem>>>(hr, du, aw, ab, wt, bt, out);
}